// round 17
// baseline (speedup 1.0000x reference)
#include <cuda_runtime.h>
#include <cuda_fp16.h>

#define Nn 100000
#define Ee 1600000
#define NB 391            // ceil(Nn/256) scan blocks
#define MTILE 128
#define GB1 ((Nn + MTILE - 1) / MTILE)   // 782
#define XS_STRIDE 136     // halves; 272B rows -> 16B aligned, ldmatrix conflict-free
#define WK_STRIDE 136
#define SMEM_BYTES ((MTILE * XS_STRIDE + 128 * WK_STRIDE) * 2)

// ---------------- scratch (device globals; allocation-free) ----------------
__device__ unsigned g_feat1h[Nn * 64]; // layer1 features, half2 pairs [N][64]
__device__ float g_el1[Nn * 4];
__device__ float g_er1[Nn * 4];
__device__ float g_h[Nn * 32];        // post head-mean + relu hidden vector
__device__ float g_feat2[Nn * 16];    // layer2 projected features
__device__ float g_el2[Nn];
__device__ float g_er2[Nn];
__device__ __half g_wh[128 * 128];    // W1 in fp16, k-major [k][col]
// CSR by dst  (g_counts statically zero-initialized; re-zeroed by agg2)
__device__ int g_counts[Nn];
__device__ int g_offs[Nn];
__device__ int g_cursor[Nn];
__device__ int g_bsums[NB];
__device__ int g_csr_src[Ee];

__device__ __forceinline__ float leaky02(float x) {
    return x > 0.f ? x : 0.2f * x;
}

// ---------------- W1 -> fp16 ------------------------------------------------
__global__ void wconv_kernel(const float* __restrict__ W1) {
    int i = blockIdx.x * blockDim.x + threadIdx.x;  // 16384 elems
    if (i < 128 * 128) g_wh[i] = __float2half(W1[i]);
}

// ---------------- GEMM1 via HMMA (m16n8k16) + el/er epilogue ---------------
__global__ void __launch_bounds__(256) gemm1_kernel(
        const float* __restrict__ x,
        const float* __restrict__ al1, const float* __restrict__ ar1) {
    extern __shared__ __half smem[];
    __half* xs = smem;                       // [MTILE][XS_STRIDE]
    __half* wk = smem + MTILE * XS_STRIDE;   // [128][WK_STRIDE]
    int tid = threadIdx.x;
    int nblk = blockIdx.x * MTILE;

    const float4* x4 = (const float4*)x;
#pragma unroll
    for (int r = 0; r < 16; r++) {
        int fi = tid + r * 256;          // float4 index 0..4095
        int row = fi >> 5;               // node 0..127
        int c4 = fi & 31;                // group of 4 k
        int n = nblk + row;
        float4 v = (n < Nn) ? x4[n * 32 + c4] : make_float4(0.f, 0.f, 0.f, 0.f);
        __half2 h0 = __floats2half2_rn(v.x, v.y);
        __half2 h1 = __floats2half2_rn(v.z, v.w);
        uint2 st;
        st.x = *(unsigned*)&h0;
        st.y = *(unsigned*)&h1;
        *(uint2*)&xs[row * XS_STRIDE + c4 * 4] = st;
    }
    const uint4* wh8 = (const uint4*)g_wh;   // 8 halves each, 2048 total
#pragma unroll
    for (int r = 0; r < 8; r++) {
        int i = tid + r * 256;           // 0..2047
        int row = i >> 4;                // k row
        int c8 = i & 15;                 // group of 8 cols
        *(uint4*)&wk[row * WK_STRIDE + c8 * 8] = wh8[i];
    }
    __syncthreads();

    int lane = tid & 31, wid = tid >> 5;
    int row0 = wid * 16;

    unsigned xs_u = (unsigned)__cvta_generic_to_shared(xs);
    unsigned wk_u = (unsigned)__cvta_generic_to_shared(wk);
    unsigned a_base = xs_u + ((row0 + (lane & 15)) * XS_STRIDE + ((lane >> 4) << 3)) * 2;
    unsigned b_base = wk_u + (((lane & 7) + (((lane >> 3) & 1) << 3)) * WK_STRIDE
                              + ((lane >> 4) << 3)) * 2;

    float c[16][4];
#pragma unroll
    for (int t = 0; t < 16; t++)
#pragma unroll
        for (int j = 0; j < 4; j++) c[t][j] = 0.f;

#pragma unroll
    for (int kc = 0; kc < 8; kc++) {
        unsigned a0r, a1r, a2r, a3r;
        asm volatile("ldmatrix.sync.aligned.m8n8.x4.shared.b16 {%0,%1,%2,%3}, [%4];"
                     : "=r"(a0r), "=r"(a1r), "=r"(a2r), "=r"(a3r)
                     : "r"(a_base + kc * 32));
#pragma unroll
        for (int np = 0; np < 8; np++) {
            unsigned b0, b1, b2, b3;
            asm volatile("ldmatrix.sync.aligned.m8n8.x4.trans.shared.b16 {%0,%1,%2,%3}, [%4];"
                         : "=r"(b0), "=r"(b1), "=r"(b2), "=r"(b3)
                         : "r"(b_base + kc * 16 * WK_STRIDE * 2 + np * 32));
            int t0 = np * 2, t1 = np * 2 + 1;
            asm volatile("mma.sync.aligned.m16n8k16.row.col.f32.f16.f16.f32 "
                         "{%0,%1,%2,%3}, {%4,%5,%6,%7}, {%8,%9}, {%0,%1,%2,%3};"
                         : "+f"(c[t0][0]), "+f"(c[t0][1]), "+f"(c[t0][2]), "+f"(c[t0][3])
                         : "r"(a0r), "r"(a1r), "r"(a2r), "r"(a3r), "r"(b0), "r"(b1));
            asm volatile("mma.sync.aligned.m16n8k16.row.col.f32.f16.f16.f32 "
                         "{%0,%1,%2,%3}, {%4,%5,%6,%7}, {%8,%9}, {%0,%1,%2,%3};"
                         : "+f"(c[t1][0]), "+f"(c[t1][1]), "+f"(c[t1][2]), "+f"(c[t1][3])
                         : "r"(a0r), "r"(a1r), "r"(a2r), "r"(a3r), "r"(b2), "r"(b3));
        }
    }

    int q = lane & 3;
    int r = lane >> 2;
    int n1 = nblk + row0 + r;
    int n2 = n1 + 8;
    float elp[8] = {0.f, 0.f, 0.f, 0.f, 0.f, 0.f, 0.f, 0.f};
    float erp[8] = {0.f, 0.f, 0.f, 0.f, 0.f, 0.f, 0.f, 0.f};
#pragma unroll
    for (int nt = 0; nt < 16; nt++) {
        int col = nt * 8 + q * 2;
        int head = nt >> 2;
        float a0 = __ldg(&al1[col]), a1 = __ldg(&al1[col + 1]);
        float r0 = __ldg(&ar1[col]), r1 = __ldg(&ar1[col + 1]);
        elp[head]     += c[nt][0] * a0 + c[nt][1] * a1;
        erp[head]     += c[nt][0] * r0 + c[nt][1] * r1;
        elp[4 + head] += c[nt][2] * a0 + c[nt][3] * a1;
        erp[4 + head] += c[nt][2] * r0 + c[nt][3] * r1;
        if (n1 < Nn) {
            __half2 hh = __floats2half2_rn(c[nt][0], c[nt][1]);
            g_feat1h[n1 * 64 + (col >> 1)] = *(unsigned*)&hh;
        }
        if (n2 < Nn) {
            __half2 hh = __floats2half2_rn(c[nt][2], c[nt][3]);
            g_feat1h[n2 * 64 + (col >> 1)] = *(unsigned*)&hh;
        }
    }
#pragma unroll
    for (int h = 0; h < 8; h++) {
        elp[h] += __shfl_xor_sync(0xffffffffu, elp[h], 1);
        elp[h] += __shfl_xor_sync(0xffffffffu, elp[h], 2);
        erp[h] += __shfl_xor_sync(0xffffffffu, erp[h], 1);
        erp[h] += __shfl_xor_sync(0xffffffffu, erp[h], 2);
    }
    if (n1 < Nn) { g_el1[n1 * 4 + q] = elp[q];     g_er1[n1 * 4 + q] = erp[q]; }
    if (n2 < Nn) { g_el1[n2 * 4 + q] = elp[4 + q]; g_er1[n2 * 4 + q] = erp[4 + q]; }
}

// ---------------- CSR build -------------------------------------------------
__global__ void hist_kernel(const int* __restrict__ dst) {
    int e = blockIdx.x * blockDim.x + threadIdx.x;
    if (e < Ee) atomicAdd(&g_counts[dst[e]], 1);
}

__global__ void scan_block_kernel() {
    __shared__ int sh[256];
    int t = threadIdx.x;
    int i = blockIdx.x * 256 + t;
    int v = (i < Nn) ? g_counts[i] : 0;
    sh[t] = v;
    __syncthreads();
    for (int off = 1; off < 256; off <<= 1) {
        int add = (t >= off) ? sh[t - off] : 0;
        __syncthreads();
        sh[t] += add;
        __syncthreads();
    }
    if (i < Nn) g_offs[i] = sh[t] - v;        // exclusive within block
    if (t == 255) g_bsums[blockIdx.x] = sh[t];
}

__global__ void scan_sums_kernel() {
    __shared__ int sh[512];
    int t = threadIdx.x;
    int v = (t < NB) ? g_bsums[t] : 0;
    sh[t] = v;
    __syncthreads();
    for (int off = 1; off < 512; off <<= 1) {
        int add = (t >= off) ? sh[t - off] : 0;
        __syncthreads();
        sh[t] += add;
        __syncthreads();
    }
    if (t < NB) g_bsums[t] = sh[t] - v;       // exclusive
}

__global__ void scan_add_kernel() {
    int i = blockIdx.x * 256 + threadIdx.x;
    if (i < Nn) {
        int o = g_offs[i] + g_bsums[i >> 8];
        g_offs[i] = o;
        g_cursor[i] = o;
    }
}

__global__ void fill_kernel(const int* __restrict__ src, const int* __restrict__ dst) {
    int e = blockIdx.x * blockDim.x + threadIdx.x;
    if (e < Ee) {
        int s = src[e];
        int p = atomicAdd(&g_cursor[dst[e]], 1);
        g_csr_src[p] = s;
    }
}

// ---------------- agg1: warp per node, 2 edges per iteration ---------------
// lanes 0-15 handle edge slot 0, lanes 16-31 slot 1; each lane covers 8 dims.
// sub = lane&15: dims sub*8..sub*8+7, head = sub>>2.
__global__ void __launch_bounds__(256) agg1_kernel(const float* __restrict__ b1) {
    int n = (blockIdx.x * blockDim.x + threadIdx.x) >> 5;
    int lane = threadIdx.x & 31;
    if (n >= Nn) return;
    int slot = lane >> 4;
    int sub = lane & 15;
    int head = sub >> 2;
    int start = g_offs[n];
    int end = start + g_counts[n];
    float er = __ldg(&g_er1[n * 4 + head]);
    float denom = 0.f;
    float acc[8] = {0.f, 0.f, 0.f, 0.f, 0.f, 0.f, 0.f, 0.f};

#pragma unroll 4
    for (int p = start; p < end; p += 2) {
        int pe = p + slot;
        bool valid = pe < end;
        int s = __ldg(&g_csr_src[valid ? pe : p]);
        float el = __ldg(&g_el1[s * 4 + head]);
        float ex = valid ? __expf(leaky02(el + er)) : 0.f;
        denom += ex;
        uint4 raw = __ldcg((const uint4*)&g_feat1h[s * 64 + sub * 4]);  // 16B/lane
        float2 f0 = __half22float2(*(__half2*)&raw.x);
        float2 f1 = __half22float2(*(__half2*)&raw.y);
        float2 f2 = __half22float2(*(__half2*)&raw.z);
        float2 f3 = __half22float2(*(__half2*)&raw.w);
        acc[0] = fmaf(ex, f0.x, acc[0]); acc[1] = fmaf(ex, f0.y, acc[1]);
        acc[2] = fmaf(ex, f1.x, acc[2]); acc[3] = fmaf(ex, f1.y, acc[3]);
        acc[4] = fmaf(ex, f2.x, acc[4]); acc[5] = fmaf(ex, f2.y, acc[5]);
        acc[6] = fmaf(ex, f3.x, acc[6]); acc[7] = fmaf(ex, f3.y, acc[7]);
    }
    // combine the two edge slots
    denom += __shfl_xor_sync(0xffffffffu, denom, 16);
#pragma unroll
    for (int j = 0; j < 8; j++)
        acc[j] += __shfl_xor_sync(0xffffffffu, acc[j], 16);
    float inv = (denom > 0.f) ? __frcp_rn(denom) : 0.f;

    float4 bv0 = *(const float4*)&b1[sub * 8];
    float4 bv1 = *(const float4*)&b1[sub * 8 + 4];
    float y[8];
    y[0] = fmaf(acc[0], inv, bv0.x); y[1] = fmaf(acc[1], inv, bv0.y);
    y[2] = fmaf(acc[2], inv, bv0.z); y[3] = fmaf(acc[3], inv, bv0.w);
    y[4] = fmaf(acc[4], inv, bv1.x); y[5] = fmaf(acc[5], inv, bv1.y);
    y[6] = fmaf(acc[6], inv, bv1.z); y[7] = fmaf(acc[7], inv, bv1.w);
    // mean over the 4 heads: lanes {sub, sub^4, sub^8, sub^12}
#pragma unroll
    for (int j = 0; j < 8; j++) {
        y[j] += __shfl_xor_sync(0xffffffffu, y[j], 4);
        y[j] += __shfl_xor_sync(0xffffffffu, y[j], 8);
    }
    if (lane < 4) {   // lanes 0-3 hold head-0 positions = dim chunks 0..3
        float4 o0 = make_float4(fmaxf(0.25f * y[0], 0.f), fmaxf(0.25f * y[1], 0.f),
                                fmaxf(0.25f * y[2], 0.f), fmaxf(0.25f * y[3], 0.f));
        float4 o1 = make_float4(fmaxf(0.25f * y[4], 0.f), fmaxf(0.25f * y[5], 0.f),
                                fmaxf(0.25f * y[6], 0.f), fmaxf(0.25f * y[7], 0.f));
        *(float4*)&g_h[n * 32 + lane * 8] = o0;
        *(float4*)&g_h[n * 32 + lane * 8 + 4] = o1;
    }
}

// ---------------- mid: GEMM2 (32->16) + el2/er2 (warp per node) ------------
__global__ void mid_kernel(const float* __restrict__ W2,
                           const float* __restrict__ al2, const float* __restrict__ ar2) {
    int n = (blockIdx.x * blockDim.x + threadIdx.x) >> 5;
    int lane = threadIdx.x & 31;   // = hidden dim d
    if (n >= Nn) return;
    float hv = g_h[n * 32 + lane];    // coalesced 128B
    float p16[16];
    const float4* wrow = (const float4*)&W2[lane * 16];
#pragma unroll
    for (int q = 0; q < 4; q++) {
        float4 w = __ldg(&wrow[q]);
        p16[q * 4 + 0] = hv * w.x;
        p16[q * 4 + 1] = hv * w.y;
        p16[q * 4 + 2] = hv * w.z;
        p16[q * 4 + 3] = hv * w.w;
    }
#pragma unroll
    for (int o = 1; o <= 16; o <<= 1)
#pragma unroll
        for (int j = 0; j < 16; j++)
            p16[j] += __shfl_xor_sync(0xffffffffu, p16[j], o);
    if (lane < 4) {
        float4 o4 = make_float4(p16[lane * 4], p16[lane * 4 + 1],
                                p16[lane * 4 + 2], p16[lane * 4 + 3]);
        *(float4*)&g_feat2[n * 16 + lane * 4] = o4;
    }
    if (lane == 0) {
        float el2 = 0.f, er2 = 0.f;
#pragma unroll
        for (int j = 0; j < 16; j++) {
            el2 = fmaf(p16[j], __ldg(&al2[j]), el2);
            er2 = fmaf(p16[j], __ldg(&ar2[j]), er2);
        }
        g_el2[n] = el2;
        g_er2[n] = er2;
    }
}

// ---------------- agg2: warp per node, 4 edges per iteration ---------------
// slot = lane>>3 (edge), sub = lane&7 (dims sub*2, sub*2+1).
__global__ void __launch_bounds__(256) agg2_kernel(const float* __restrict__ b2,
                                                   float* __restrict__ out) {
    int n = (blockIdx.x * blockDim.x + threadIdx.x) >> 5;
    int lane = threadIdx.x & 31;
    if (n >= Nn) return;
    int slot = lane >> 3;
    int sub = lane & 7;
    int start = g_offs[n];
    int end = start + g_counts[n];
    float er = __ldg(&g_er2[n]);
    float denom = 0.f, a0 = 0.f, a1 = 0.f;

#pragma unroll 4
    for (int p = start; p < end; p += 4) {
        int pe = p + slot;
        bool valid = pe < end;
        int s = __ldg(&g_csr_src[valid ? pe : p]);
        float el = __ldg(&g_el2[s]);
        float ex = valid ? __expf(leaky02(el + er)) : 0.f;
        denom += ex;
        float2 f = __ldcg((const float2*)&g_feat2[s * 16 + sub * 2]);
        a0 = fmaf(ex, f.x, a0);
        a1 = fmaf(ex, f.y, a1);
    }
    // combine the 4 edge slots
    denom += __shfl_xor_sync(0xffffffffu, denom, 8);
    denom += __shfl_xor_sync(0xffffffffu, denom, 16);
    a0 += __shfl_xor_sync(0xffffffffu, a0, 8);
    a0 += __shfl_xor_sync(0xffffffffu, a0, 16);
    a1 += __shfl_xor_sync(0xffffffffu, a1, 8);
    a1 += __shfl_xor_sync(0xffffffffu, a1, 16);
    float inv = (denom > 0.f) ? __frcp_rn(denom) : 0.f;
    if (lane < 8) {
        float2 o = make_float2(fmaf(a0, inv, __ldg(&b2[sub * 2])),
                               fmaf(a1, inv, __ldg(&b2[sub * 2 + 1])));
        *(float2*)&out[n * 16 + sub * 2] = o;
    }
    // reset counts for the next graph replay (statically zero on first run)
    if (lane == 0) g_counts[n] = 0;
}

// ---------------- launch ----------------------------------------------------
extern "C" void kernel_launch(void* const* d_in, const int* in_sizes, int n_in,
                              void* d_out, int out_size) {
    const float* x   = (const float*)d_in[0];
    const int*   src = (const int*)d_in[1];
    const int*   dst = (const int*)d_in[2];
    const float* W1  = (const float*)d_in[3];
    const float* al1 = (const float*)d_in[4];
    const float* ar1 = (const float*)d_in[5];
    const float* b1  = (const float*)d_in[6];
    const float* W2  = (const float*)d_in[7];
    const float* al2 = (const float*)d_in[8];
    const float* ar2 = (const float*)d_in[9];
    const float* b2  = (const float*)d_in[10];
    float* out = (float*)d_out;

    // one-time host resources (no device memory; same GPU work every call)
    static cudaStream_t s2 = 0;
    static cudaEvent_t ev_fork = 0, ev_join = 0;
    if (s2 == 0) {
        cudaStreamCreateWithFlags(&s2, cudaStreamNonBlocking);
        cudaEventCreateWithFlags(&ev_fork, cudaEventDisableTiming);
        cudaEventCreateWithFlags(&ev_join, cudaEventDisableTiming);
        cudaFuncSetAttribute(gemm1_kernel,
                             cudaFuncAttributeMaxDynamicSharedMemorySize, SMEM_BYTES);
    }

    // fork: GEMM chain on s2, CSR chain on the capture stream
    cudaEventRecord(ev_fork, 0);
    cudaStreamWaitEvent(s2, ev_fork, 0);

    wconv_kernel<<<64, 256, 0, s2>>>(W1);
    gemm1_kernel<<<GB1, 256, SMEM_BYTES, s2>>>(x, al1, ar1);
    cudaEventRecord(ev_join, s2);

    hist_kernel<<<(Ee + 255) / 256, 256>>>(dst);
    scan_block_kernel<<<NB, 256>>>();
    scan_sums_kernel<<<1, 512>>>();
    scan_add_kernel<<<NB, 256>>>();
    fill_kernel<<<(Ee + 255) / 256, 256>>>(src, dst);

    // join: agg1 needs both fill (stream 0) and gemm1 (s2)
    cudaStreamWaitEvent(0, ev_join, 0);

    agg1_kernel<<<(Nn * 32 + 255) / 256, 256>>>(b1);
    mid_kernel<<<(Nn * 32 + 255) / 256, 256>>>(W2, al2, ar2);
    agg2_kernel<<<(Nn * 32 + 255) / 256, 256>>>(b2, out);
}